// round 15
// baseline (speedup 1.0000x reference)
#include <cuda_runtime.h>
#include <cuda_bf16.h>
#include <cstdint>

// Problem constants
#define BQ 8
#define TQ 1024
#define CQ 768
#define HQ 8
#define DQ 96
#define C3 2304          // 3*C
#define MROWS (BQ*TQ)    // 8192
#define GK 768           // K dim for both GEMMs
#define NCH 12           // 768 / 64 K-chunks

// ---------------------------------------------------------------------------
// Scratch (device globals; no cudaMalloc allowed)
// ---------------------------------------------------------------------------
__device__ __nv_bfloat16 g_qkvh[MROWS * C3], g_qkvl[MROWS * C3]; // qkv hi/lo
__device__ __nv_bfloat16 g_xh[MROWS * CQ], g_xl[MROWS * CQ];
__device__ __nv_bfloat16 g_yh[MROWS * CQ], g_yl[MROWS * CQ];     // attn out hi/lo
__device__ __nv_bfloat16 g_wah[C3 * CQ],   g_wal[C3 * CQ];
__device__ __nv_bfloat16 g_wph[CQ * CQ],   g_wpl[CQ * CQ];

// ---------------------------------------------------------------------------
// Portable PTX helpers (baseline PTX, legal on compute_103)
// ---------------------------------------------------------------------------
__device__ __forceinline__ uint32_t smem_u32(const void* p) {
    uint32_t a;
    asm("{ .reg .u64 t; cvta.to.shared.u64 t, %1; cvt.u32.u64 %0, t; }"
        : "=r"(a) : "l"(p));
    return a;
}

#define CP_ASYNC16(dst, src) \
    asm volatile("cp.async.cg.shared.global [%0], [%1], 16;" \
                 :: "r"(dst), "l"(src) : "memory")
#define CP_COMMIT() asm volatile("cp.async.commit_group;" ::: "memory")
#define CP_WAIT1()  asm volatile("cp.async.wait_group 1;" ::: "memory")
#define CP_WAIT0()  asm volatile("cp.async.wait_group 0;" ::: "memory")

#define LDSM4(r, addr) \
    asm volatile("ldmatrix.sync.aligned.m8n8.x4.shared.b16 {%0,%1,%2,%3}, [%4];" \
                 : "=r"((r)[0]), "=r"((r)[1]), "=r"((r)[2]), "=r"((r)[3]) \
                 : "r"(addr))

#define LDSM4T(r, addr) \
    asm volatile("ldmatrix.sync.aligned.m8n8.x4.trans.shared.b16 {%0,%1,%2,%3}, [%4];" \
                 : "=r"((r)[0]), "=r"((r)[1]), "=r"((r)[2]), "=r"((r)[3]) \
                 : "r"(addr))

#define MMA16816(d, a, b0, b1) \
    asm volatile("mma.sync.aligned.m16n8k16.row.col.f32.bf16.bf16.f32 " \
                 "{%0,%1,%2,%3}, {%4,%5,%6,%7}, {%8,%9}, {%0,%1,%2,%3};" \
                 : "+f"((d)[0]), "+f"((d)[1]), "+f"((d)[2]), "+f"((d)[3]) \
                 : "r"((a)[0]), "r"((a)[1]), "r"((a)[2]), "r"((a)[3]), \
                   "r"(b0), "r"(b1))

// ---------------------------------------------------------------------------
// Decompose: x -> (hi, lo) bf16 pair
// ---------------------------------------------------------------------------
__global__ void __launch_bounds__(256)
decompose_kernel(const float4* __restrict__ src,
                 uint2* __restrict__ hi, uint2* __restrict__ lo, int n4)
{
    int i = blockIdx.x * 256 + threadIdx.x;
    if (i >= n4) return;
    float4 v = src[i];
    float f[4] = {v.x, v.y, v.z, v.w};
    union { __nv_bfloat16 h[4]; uint2 u; } H, L;
#pragma unroll
    for (int j = 0; j < 4; j++) {
        H.h[j] = __float2bfloat16(f[j]);
        L.h[j] = __float2bfloat16(f[j] - __bfloat162float(H.h[j]));
    }
    hi[i] = H.u;
    lo[i] = L.u;
}

// ---------------------------------------------------------------------------
// bf16x3 NT GEMM via mma.sync (HMMA). mode 0: f32 out. mode 1: hi/lo bf16 out.
// R15: explicit fragment double-buffering — prefetch ks+1 fragments (12 LDSM4)
// while issuing ks's 48 MMAs so crossbar overlaps tensor pipe.
// ---------------------------------------------------------------------------
#define TILEB 16384
#define STAGEB (4 * TILEB)
#define GEMM_SMEM (2 * STAGEB)   // 131072

__global__ void __launch_bounds__(256, 1)
gemm_bf16x3_mma(const __nv_bfloat16* __restrict__ Ah,
                const __nv_bfloat16* __restrict__ Al,
                const __nv_bfloat16* __restrict__ Bh,
                const __nv_bfloat16* __restrict__ Bl,
                const float* __restrict__ bias,
                float* __restrict__ C,
                __nv_bfloat16* __restrict__ Ch,
                __nv_bfloat16* __restrict__ Cl,
                int N, int mode)
{
    extern __shared__ char smem[];
    const uint32_t sb = smem_u32(smem);
    const int tid = threadIdx.x;
    const int lane = tid & 31;
    const int w = tid >> 5;
    const int wm = w & 3;
    const int wn = w >> 2;
    const int bm0 = blockIdx.y * 128;
    const int bn0 = blockIdx.x * 128;

    const __nv_bfloat16* src0 = Ah + (long long)bm0 * GK;
    const __nv_bfloat16* src1 = Al + (long long)bm0 * GK;
    const __nv_bfloat16* src2 = Bh + (long long)bn0 * GK;
    const __nv_bfloat16* src3 = Bl + (long long)bn0 * GK;

    const int trow = (lane & 7) + ((lane >> 3) & 1) * 8;
    const int tseg = lane >> 4;

    // Per-thread LDSM row-offsets (within tile) for A (2 blocks) and B (4)
    uint32_t offA[2], offB[4];
#pragma unroll
    for (int mt = 0; mt < 2; mt++) {
        int r = wm * 32 + mt * 16 + trow;
        offA[mt] = r * 128;              // + swizzled seg added per-ks
    }
#pragma unroll
    for (int np = 0; np < 4; np++) {
        int r = wn * 64 + np * 16 + trow;
        offB[np] = r * 128;
    }
    const int rA7[2] = {(wm * 32 + trow) & 7, (wm * 32 + 16 + trow) & 7};
    const int rB7[4] = {(wn * 64 + trow) & 7, (wn * 64 + 16 + trow) & 7,
                        (wn * 64 + 32 + trow) & 7, (wn * 64 + 48 + trow) & 7};

    float acc[2][8][4];
#pragma unroll
    for (int mt = 0; mt < 2; mt++)
#pragma unroll
        for (int nt = 0; nt < 8; nt++)
#pragma unroll
            for (int j = 0; j < 4; j++) acc[mt][nt][j] = 0.f;

#define STAGE_LOAD(c, buf)                                                    \
    do {                                                                      \
        const uint32_t base_ = sb + (buf) * STAGEB;                           \
        const __nv_bfloat16* sp_[4] = {src0 + (c) * 64, src1 + (c) * 64,      \
                                       src2 + (c) * 64, src3 + (c) * 64};     \
        _Pragma("unroll")                                                     \
        for (int t_ = 0; t_ < 4; t_++) {                                      \
            const uint32_t tb_ = base_ + t_ * TILEB;                          \
            _Pragma("unroll")                                                 \
            for (int it_ = 0; it_ < 4; it_++) {                               \
                int i_ = tid + it_ * 256;                                     \
                int r_ = i_ >> 3, sg_ = i_ & 7;                               \
                uint32_t dst_ = tb_ + r_ * 128 + ((sg_ ^ (r_ & 7)) << 4);     \
                const void* s_ = sp_[t_] + (long long)r_ * GK + sg_ * 8;      \
                CP_ASYNC16(dst_, s_);                                         \
            }                                                                 \
        }                                                                     \
    } while (0)

    // Fragment loader for one k16 step (ks = 0..3) from stage base tAh
#define FRAG_LOAD(dst_a_h, dst_a_l, dst_b_h, dst_b_l, tAh_, ks_)              \
    do {                                                                      \
        const int segk_ = 2 * (ks_) + tseg;                                   \
        _Pragma("unroll")                                                     \
        for (int mt_ = 0; mt_ < 2; mt_++) {                                   \
            uint32_t o_ = offA[mt_] + ((segk_ ^ rA7[mt_]) << 4);              \
            LDSM4(dst_a_h[mt_], (tAh_) + o_);                                 \
            LDSM4(dst_a_l[mt_], (tAh_) + TILEB + o_);                         \
        }                                                                     \
        _Pragma("unroll")                                                     \
        for (int np_ = 0; np_ < 4; np_++) {                                   \
            uint32_t o_ = offB[np_] + ((segk_ ^ rB7[np_]) << 4);              \
            LDSM4(dst_b_h[np_], (tAh_) + 2 * TILEB + o_);                     \
            LDSM4(dst_b_l[np_], (tAh_) + 3 * TILEB + o_);                     \
        }                                                                     \
    } while (0)

#define FRAG_MMA(a_h, a_l, b_h, b_l)                                          \
    do {                                                                      \
        _Pragma("unroll")                                                     \
        for (int mt_ = 0; mt_ < 2; mt_++) {                                   \
            _Pragma("unroll")                                                 \
            for (int np_ = 0; np_ < 4; np_++) {                               \
                MMA16816(acc[mt_][2 * np_],     a_h[mt_], b_h[np_][0], b_h[np_][2]); \
                MMA16816(acc[mt_][2 * np_ + 1], a_h[mt_], b_h[np_][1], b_h[np_][3]); \
                MMA16816(acc[mt_][2 * np_],     a_h[mt_], b_l[np_][0], b_l[np_][2]); \
                MMA16816(acc[mt_][2 * np_ + 1], a_h[mt_], b_l[np_][1], b_l[np_][3]); \
                MMA16816(acc[mt_][2 * np_],     a_l[mt_], b_h[np_][0], b_h[np_][2]); \
                MMA16816(acc[mt_][2 * np_ + 1], a_l[mt_], b_h[np_][1], b_h[np_][3]); \
            }                                                                 \
        }                                                                     \
    } while (0)

    STAGE_LOAD(0, 0);
    CP_COMMIT();

    // Double-buffered fragment registers
    uint32_t ah0[2][4], al0[2][4], bh0[4][4], bl0[4][4];
    uint32_t ah1[2][4], al1[2][4], bh1[4][4], bl1[4][4];

    for (int c = 0; c < NCH; c++) {
        const int buf = c & 1;
        if (c + 1 < NCH) {
            STAGE_LOAD(c + 1, buf ^ 1);
            CP_COMMIT();
            CP_WAIT1();
        } else {
            CP_WAIT0();
        }
        __syncthreads();

        const uint32_t tAh = sb + buf * STAGEB;

        // Software-pipelined: prefetch ks+1 fragments during ks MMAs
        FRAG_LOAD(ah0, al0, bh0, bl0, tAh, 0);
        FRAG_LOAD(ah1, al1, bh1, bl1, tAh, 1);
        FRAG_MMA(ah0, al0, bh0, bl0);
        FRAG_LOAD(ah0, al0, bh0, bl0, tAh, 2);
        FRAG_MMA(ah1, al1, bh1, bl1);
        FRAG_LOAD(ah1, al1, bh1, bl1, tAh, 3);
        FRAG_MMA(ah0, al0, bh0, bl0);
        FRAG_MMA(ah1, al1, bh1, bl1);

        __syncthreads();
    }

    const int g = lane >> 2, tg = lane & 3;
#pragma unroll
    for (int mt = 0; mt < 2; mt++) {
        const long long row0 = bm0 + wm * 32 + mt * 16 + g;
#pragma unroll
        for (int nt = 0; nt < 8; nt++) {
            const int col = bn0 + wn * 64 + nt * 8 + tg * 2;
            float2 bi = *(const float2*)&bias[col];
            float o[4] = {acc[mt][nt][0] + bi.x, acc[mt][nt][1] + bi.y,
                          acc[mt][nt][2] + bi.x, acc[mt][nt][3] + bi.y};
            if (mode == 0) {
                *(float2*)&C[row0 * N + col]       = make_float2(o[0], o[1]);
                *(float2*)&C[(row0 + 8) * N + col] = make_float2(o[2], o[3]);
            } else {
                union { __nv_bfloat16 b[2]; uint32_t u; } H0, L0, H1, L1;
#pragma unroll
                for (int z = 0; z < 2; z++) {
                    H0.b[z] = __float2bfloat16(o[z]);
                    L0.b[z] = __float2bfloat16(o[z] - __bfloat162float(H0.b[z]));
                    H1.b[z] = __float2bfloat16(o[z + 2]);
                    L1.b[z] = __float2bfloat16(o[z + 2] - __bfloat162float(H1.b[z]));
                }
                *(uint32_t*)&Ch[row0 * N + col]       = H0.u;
                *(uint32_t*)&Cl[row0 * N + col]       = L0.u;
                *(uint32_t*)&Ch[(row0 + 8) * N + col] = H1.u;
                *(uint32_t*)&Cl[(row0 + 8) * N + col] = L1.u;
            }
        }
    }
}

// ---------------------------------------------------------------------------
// Full-HMMA flash attention (causal) — unchanged from R14 (passing).
// ---------------------------------------------------------------------------
#define KSTR 208
#define QTB  (64 * KSTR)             // 13312
#define PSTR 144
#define OFF_QH 0
#define OFF_QL (1 * QTB)
#define OFF_KH (2 * QTB)
#define OFF_KL (3 * QTB)
#define OFF_VH (4 * QTB)
#define OFF_VL (5 * QTB)             // 66560
#define OFF_S  (6 * QTB)             // 79872, f32 64x64
#define OFF_PH (OFF_S + 64 * 64 * 4) // 96256
#define OFF_PL (OFF_PH + 64 * PSTR)  // 105472
#define OFF_AL (OFF_PL + 64 * PSTR)  // 114688, 64 f32 (alpha, reused as 1/l)
#define ATT_SMEM (OFF_AL + 256)      // 114944

__global__ void __launch_bounds__(256, 2)
attn_kernel()
{
    extern __shared__ char smc[];
    const uint32_t sb = smem_u32(smc);
    float* Ss = (float*)(smc + OFF_S);
    float* Al = (float*)(smc + OFF_AL);

    const int tid = threadIdx.x;
    const int lane = tid & 31;
    const int w = tid >> 5;
    const int wm = w & 3;
    const int wn = w >> 2;
    const int qt = blockIdx.x;
    const int bh = blockIdx.y;
    const int b = bh >> 3, h = bh & 7;
    const int q0 = qt * 64;

    const int trow = (lane & 7) + ((lane >> 3) & 1) * 8;
    const int tseg = lane >> 4;
    const int g = lane >> 2, tg = lane & 3;
    const float scale = 0.1020620726159658f; // 1/sqrt(96)

    const long long hbase = (long long)(b * TQ) * C3 + h * DQ;

    for (int i = tid; i < 64 * 12; i += 256) {
        int r = i / 12, sg = i % 12;
        long long src = hbase + (long long)(q0 + r) * C3 + sg * 8;
        CP_ASYNC16(sb + OFF_QH + r * KSTR + sg * 16, g_qkvh + src);
        CP_ASYNC16(sb + OFF_QL + r * KSTR + sg * 16, g_qkvl + src);
    }
    CP_COMMIT();

    float m_i[8], l_i[8];
#pragma unroll
    for (int qr = 0; qr < 8; qr++) { m_i[qr] = -1e30f; l_i[qr] = 0.f; }

    float pacc[6][4];
#pragma unroll
    for (int t = 0; t < 6; t++)
#pragma unroll
        for (int z = 0; z < 4; z++) pacc[t][z] = 0.f;

    const uint32_t vtb = sb + OFF_VH
        + (((lane >> 3) & 1) * 8 + (lane & 7)) * KSTR
        + (lane >> 4) * 16 + wn * 48 * 2;

    for (int j = 0; j <= qt; j++) {
        __syncthreads();
        const int k0r = j * 64;
        for (int i = tid; i < 64 * 12; i += 256) {
            int r = i / 12, sg = i % 12;
            long long srck = hbase + (long long)(k0r + r) * C3 + 768 + sg * 8;
            long long srcv = srck + 768;
            CP_ASYNC16(sb + OFF_KH + r * KSTR + sg * 16, g_qkvh + srck);
            CP_ASYNC16(sb + OFF_KL + r * KSTR + sg * 16, g_qkvl + srck);
            CP_ASYNC16(sb + OFF_VH + r * KSTR + sg * 16, g_qkvh + srcv);
            CP_ASYNC16(sb + OFF_VL + r * KSTR + sg * 16, g_qkvl + srcv);
        }
        CP_COMMIT();
        CP_WAIT0();
        __syncthreads();

        {
            float sacc[4][4];
#pragma unroll
            for (int t = 0; t < 4; t++)
#pragma unroll
                for (int z = 0; z < 4; z++) sacc[t][z] = 0.f;

            const uint32_t abase = sb + OFF_QH + (wm * 16 + trow) * KSTR;
#pragma unroll
            for (int kc = 0; kc < 6; kc++) {
                const uint32_t ko = (2 * kc + tseg) * 16;
                uint32_t qh4[4], ql4[4];
                LDSM4(qh4, abase + ko);
                LDSM4(ql4, abase + QTB + ko);
#pragma unroll
                for (int nb = 0; nb < 2; nb++) {
                    const uint32_t bb = sb + OFF_KH
                        + (wn * 32 + nb * 16 + trow) * KSTR + ko;
                    uint32_t kh4[4], kl4[4];
                    LDSM4(kh4, bb);
                    LDSM4(kl4, bb + QTB);
                    MMA16816(sacc[2 * nb],     qh4, kh4[0], kh4[2]);
                    MMA16816(sacc[2 * nb + 1], qh4, kh4[1], kh4[3]);
                    MMA16816(sacc[2 * nb],     qh4, kl4[0], kl4[2]);
                    MMA16816(sacc[2 * nb + 1], qh4, kl4[1], kl4[3]);
                    MMA16816(sacc[2 * nb],     ql4, kh4[0], kh4[2]);
                    MMA16816(sacc[2 * nb + 1], ql4, kh4[1], kh4[3]);
                }
            }
#pragma unroll
            for (int t = 0; t < 4; t++) {
                const int r0 = wm * 16 + g, c = wn * 32 + t * 8 + tg * 2;
                *(float2*)&Ss[r0 * 64 + c] =
                    make_float2(sacc[t][0] * scale, sacc[t][1] * scale);
                *(float2*)&Ss[(r0 + 8) * 64 + c] =
                    make_float2(sacc[t][2] * scale, sacc[t][3] * scale);
            }
        }
        __syncthreads();

        const bool diag = (j == qt);
#pragma unroll
        for (int qr = 0; qr < 8; qr++) {
            const int row = w * 8 + qr;
            const int qg = q0 + row;
            float s0 = Ss[row * 64 + lane];
            float s1 = Ss[row * 64 + lane + 32];
            if (diag) {
                if (k0r + lane      > qg) s0 = -1e30f;
                if (k0r + lane + 32 > qg) s1 = -1e30f;
            }
            float mx = fmaxf(s0, s1);
#pragma unroll
            for (int o = 16; o; o >>= 1)
                mx = fmaxf(mx, __shfl_xor_sync(0xffffffffu, mx, o));
            float m_new = fmaxf(m_i[qr], mx);
            float p0 = __expf(s0 - m_new);
            float p1 = __expf(s1 - m_new);
            float rs = p0 + p1;
#pragma unroll
            for (int o = 16; o; o >>= 1)
                rs += __shfl_xor_sync(0xffffffffu, rs, o);
            float alpha = __expf(m_i[qr] - m_new);
            l_i[qr] = l_i[qr] * alpha + rs;
            m_i[qr] = m_new;
            __nv_bfloat16 h0 = __float2bfloat16(p0);
            __nv_bfloat16 h1 = __float2bfloat16(p1);
            *(__nv_bfloat16*)(smc + OFF_PH + row * PSTR + lane * 2)        = h0;
            *(__nv_bfloat16*)(smc + OFF_PH + row * PSTR + (lane + 32) * 2) = h1;
            *(__nv_bfloat16*)(smc + OFF_PL + row * PSTR + lane * 2) =
                __float2bfloat16(p0 - __bfloat162float(h0));
            *(__nv_bfloat16*)(smc + OFF_PL + row * PSTR + (lane + 32) * 2) =
                __float2bfloat16(p1 - __bfloat162float(h1));
            if (lane == 0) Al[row] = alpha;
        }
        __syncthreads();

        {
            const float a0 = Al[wm * 16 + g];
            const float a1 = Al[wm * 16 + g + 8];
#pragma unroll
            for (int t = 0; t < 6; t++) {
                pacc[t][0] *= a0; pacc[t][1] *= a0;
                pacc[t][2] *= a1; pacc[t][3] *= a1;
            }
            const uint32_t pbase = sb + OFF_PH + (wm * 16 + trow) * PSTR;
#pragma unroll
            for (int kc = 0; kc < 4; kc++) {
                const uint32_t ko = (2 * kc + tseg) * 16;
                uint32_t ph4[4], pl4[4];
                LDSM4(ph4, pbase + ko);
                LDSM4(pl4, pbase + 64 * PSTR + ko);
#pragma unroll
                for (int nb = 0; nb < 3; nb++) {
                    const uint32_t vb = vtb + kc * 16 * KSTR + nb * 32;
                    uint32_t vh4[4], vl4[4];
                    LDSM4T(vh4, vb);
                    LDSM4T(vl4, vb + QTB);
                    MMA16816(pacc[2 * nb],     ph4, vh4[0], vh4[1]);
                    MMA16816(pacc[2 * nb + 1], ph4, vh4[2], vh4[3]);
                    MMA16816(pacc[2 * nb],     ph4, vl4[0], vl4[1]);
                    MMA16816(pacc[2 * nb + 1], ph4, vl4[2], vl4[3]);
                    MMA16816(pacc[2 * nb],     pl4, vh4[0], vh4[1]);
                    MMA16816(pacc[2 * nb + 1], pl4, vh4[2], vh4[3]);
                }
            }
        }
    }

    __syncthreads();
#pragma unroll
    for (int qr = 0; qr < 8; qr++)
        if (lane == 0) Al[w * 8 + qr] = 1.0f / l_i[qr];
    __syncthreads();

    {
        const float n0 = Al[wm * 16 + g];
        const float n1 = Al[wm * 16 + g + 8];
        const long long r0 = (long long)(b * TQ + q0 + wm * 16 + g);
#pragma unroll
        for (int t = 0; t < 6; t++) {
            const int c = wn * 48 + t * 8 + tg * 2;
            float o[4] = {pacc[t][0] * n0, pacc[t][1] * n0,
                          pacc[t][2] * n1, pacc[t][3] * n1};
            union { __nv_bfloat16 b2[2]; uint32_t u; } H0, L0, H1, L1;
#pragma unroll
            for (int z = 0; z < 2; z++) {
                H0.b2[z] = __float2bfloat16(o[z]);
                L0.b2[z] = __float2bfloat16(o[z] - __bfloat162float(H0.b2[z]));
                H1.b2[z] = __float2bfloat16(o[z + 2]);
                L1.b2[z] = __float2bfloat16(o[z + 2] - __bfloat162float(H1.b2[z]));
            }
            *(uint32_t*)&g_yh[r0 * CQ + h * DQ + c]       = H0.u;
            *(uint32_t*)&g_yl[r0 * CQ + h * DQ + c]       = L0.u;
            *(uint32_t*)&g_yh[(r0 + 8) * CQ + h * DQ + c] = H1.u;
            *(uint32_t*)&g_yl[(r0 + 8) * CQ + h * DQ + c] = L1.u;
        }
    }
}

// ---------------------------------------------------------------------------
// Launch
// ---------------------------------------------------------------------------
extern "C" void kernel_launch(void* const* d_in, const int* in_sizes, int n_in,
                              void* d_out, int out_size)
{
    const float* x      = (const float*)d_in[0];
    const float* w_attn = (const float*)d_in[1];
    const float* b_attn = (const float*)d_in[2];
    const float* w_proj = (const float*)d_in[3];
    const float* b_proj = (const float*)d_in[4];
    float* out = (float*)d_out;

    __nv_bfloat16 *qkvh, *qkvl, *xh, *xl, *yh, *yl, *wah, *wal, *wph, *wpl;
    cudaGetSymbolAddress((void**)&qkvh, g_qkvh);
    cudaGetSymbolAddress((void**)&qkvl, g_qkvl);
    cudaGetSymbolAddress((void**)&xh,  g_xh);
    cudaGetSymbolAddress((void**)&xl,  g_xl);
    cudaGetSymbolAddress((void**)&yh,  g_yh);
    cudaGetSymbolAddress((void**)&yl,  g_yl);
    cudaGetSymbolAddress((void**)&wah, g_wah);
    cudaGetSymbolAddress((void**)&wal, g_wal);
    cudaGetSymbolAddress((void**)&wph, g_wph);
    cudaGetSymbolAddress((void**)&wpl, g_wpl);

    cudaFuncSetAttribute(gemm_bf16x3_mma,
                         cudaFuncAttributeMaxDynamicSharedMemorySize, GEMM_SMEM);
    cudaFuncSetAttribute(attn_kernel,
                         cudaFuncAttributeMaxDynamicSharedMemorySize, ATT_SMEM);

    // 0) hi/lo bf16 decompositions of inputs/weights
    {
        int n4 = MROWS * CQ / 4;
        decompose_kernel<<<(n4 + 255) / 256, 256>>>(
            (const float4*)x, (uint2*)xh, (uint2*)xl, n4);
        n4 = C3 * CQ / 4;
        decompose_kernel<<<(n4 + 255) / 256, 256>>>(
            (const float4*)w_attn, (uint2*)wah, (uint2*)wal, n4);
        n4 = CQ * CQ / 4;
        decompose_kernel<<<(n4 + 255) / 256, 256>>>(
            (const float4*)w_proj, (uint2*)wph, (uint2*)wpl, n4);
    }

    // 1) QKV projection -> hi/lo bf16 qkv directly (mode 1)
    gemm_bf16x3_mma<<<dim3(C3 / 128, MROWS / 128), 256, GEMM_SMEM>>>(
        xh, xl, wah, wal, b_attn, nullptr, qkvh, qkvl, C3, 1);

    // 2) Full-HMMA causal flash attention -> hi/lo bf16 y directly
    attn_kernel<<<dim3(TQ / 64, BQ * HQ), 256, ATT_SMEM>>>();

    // 3) Output projection -> f32 out (mode 0)
    gemm_bf16x3_mma<<<dim3(CQ / 128, MROWS / 128), 256, GEMM_SMEM>>>(
        yh, yl, wph, wpl, b_proj, out, nullptr, nullptr, CQ, 0);
}